// round 4
// baseline (speedup 1.0000x reference)
#include <cuda_runtime.h>

#define N_NODES 50000
#define N_EDGES 800000
#define D_FEAT  64
#define ROWS_PER_BLOCK 8
#define CHUNK 8

// Precomputed CSR row pointers (lower bounds into sorted row_idx).
__device__ int g_row_ptr[N_NODES + 1];

// Kernel A: one thread per boundary, independent binary searches.
__global__ __launch_bounds__(256)
void build_row_ptr_kernel(const int* __restrict__ row_idx) {
    const int t = blockIdx.x * blockDim.x + threadIdx.x;
    if (t > N_NODES) return;
    int lo = 0, hi = N_EDGES;
    while (lo < hi) {
        const int mid = (lo + hi) >> 1;
        if (__ldg(row_idx + mid) < t) lo = mid + 1; else hi = mid;
    }
    g_row_ptr[t] = lo;
}

// Kernel B: warp-per-row SpMM, 32 lanes x float2 = 64 dims.
// No tail loop: every iteration runs a full CHUNK with clamped indices
// (always-valid addresses -> unpredicated back-to-back LDGs, MLP=CHUNK),
// and out-of-range slots contribute v=0 via select (no branches).
__global__ __launch_bounds__(ROWS_PER_BLOCK * 32)
void gcn_spmm_kernel(const int* __restrict__ col_idx,
                     const float* __restrict__ vals,
                     const float* __restrict__ embeds,
                     float* __restrict__ out) {
    const int tid  = threadIdx.x;
    const int wid  = tid >> 5;
    const int lane = tid & 31;
    const int row  = blockIdx.x * ROWS_PER_BLOCK + wid;

    const int start = __ldg(&g_row_ptr[row]);
    const int end   = __ldg(&g_row_ptr[row + 1]);
    const int endm1 = end - 1;

    const float2* __restrict__ emb2 = reinterpret_cast<const float2*>(embeds);

    float2 acc = make_float2(0.0f, 0.0f);

    for (int e = start; e < end; e += CHUNK) {
        float  v[CHUNK];
        float2 x[CHUNK];
        // 8 independent load chains; clamped index keeps every address valid
        // so ptxas emits straight-line unpredicated LDGs.
        #pragma unroll
        for (int i = 0; i < CHUNK; i++) {
            const int idx = min(e + i, endm1);
            const int c   = __ldg(col_idx + idx);
            x[i] = __ldg(emb2 + (size_t)c * 32 + lane);
            v[i] = __ldg(vals + idx);
        }
        #pragma unroll
        for (int i = 0; i < CHUNK; i++) {
            const float vv = (e + i < end) ? v[i] : 0.0f;   // FSEL, no branch
            acc.x = fmaf(vv, x[i].x, acc.x);
            acc.y = fmaf(vv, x[i].y, acc.y);
        }
    }

    // Coalesced 256B row store; empty rows write zeros over the poison.
    reinterpret_cast<float2*>(out)[(size_t)row * 32 + lane] = acc;
}

extern "C" void kernel_launch(void* const* d_in, const int* in_sizes, int n_in,
                              void* d_out, int out_size) {
    const int*   row_idx = (const int*)  d_in[0];
    const int*   col_idx = (const int*)  d_in[1];
    const float* vals    = (const float*)d_in[2];
    const float* embeds  = (const float*)d_in[3];
    float*       out     = (float*)d_out;

    build_row_ptr_kernel<<<(N_NODES + 1 + 255) / 256, 256>>>(row_idx);

    const int blocks = N_NODES / ROWS_PER_BLOCK;   // 6250
    gcn_spmm_kernel<<<blocks, ROWS_PER_BLOCK * 32>>>(col_idx, vals, embeds, out);
}

// round 5
// speedup vs baseline: 1.2487x; 1.2487x over previous
#include <cuda_runtime.h>

#define N_NODES 50000
#define N_EDGES 800000
#define D_FEAT  64
#define ROWS_PER_BLOCK 8
#define PAIRS 4   // 4 LDG.128 gathers per chunk = 8 edges per chunk

// Precomputed CSR row pointers (lower bounds into sorted row_idx).
__device__ int g_row_ptr[N_NODES + 1];

// Kernel A: one thread per boundary, independent binary searches.
__global__ __launch_bounds__(256)
void build_row_ptr_kernel(const int* __restrict__ row_idx) {
    const int t = blockIdx.x * blockDim.x + threadIdx.x;
    if (t > N_NODES) return;
    int lo = 0, hi = N_EDGES;
    while (lo < hi) {
        const int mid = (lo + hi) >> 1;
        if (__ldg(row_idx + mid) < t) lo = mid + 1; else hi = mid;
    }
    g_row_ptr[t] = lo;
}

// Kernel B: warp-per-row SpMM, float4 on 16 lanes; the two half-warps
// process edges e (lanes 0-15) and e+1 (lanes 16-31) in the SAME LDG.128,
// halving LDG instruction count (the binding resource per R4 analysis).
// Tail handled by index clamp + FSEL-zeroed value (addresses always valid
// -> unpredicated straight-line loads).
__global__ __launch_bounds__(ROWS_PER_BLOCK * 32)
void gcn_spmm_kernel(const int* __restrict__ col_idx,
                     const float* __restrict__ vals,
                     const float* __restrict__ embeds,
                     float* __restrict__ out) {
    const int tid  = threadIdx.x;
    const int wid  = tid >> 5;
    const int lane = tid & 31;
    const int half = lane >> 4;        // 0: even edges, 1: odd edges
    const int l16  = lane & 15;        // dim group: floats [4*l16 .. 4*l16+3]
    const int row  = blockIdx.x * ROWS_PER_BLOCK + wid;

    const int start = __ldg(&g_row_ptr[row]);
    const int end   = __ldg(&g_row_ptr[row + 1]);
    const int endm1 = end - 1;         // only used when loop body runs (end > start)

    const float4* __restrict__ emb4 = reinterpret_cast<const float4*>(embeds);

    float4 acc = make_float4(0.0f, 0.0f, 0.0f, 0.0f);

    for (int e = start; e < end; e += 2 * PAIRS) {
        float  v[PAIRS];
        float4 x[PAIRS];
        #pragma unroll
        for (int i = 0; i < PAIRS; i++) {
            const int eidx = e + 2 * i + half;
            const int idx  = min(eidx, endm1);          // always valid
            const int c    = __ldg(col_idx + idx);      // 2 addrs/warp, 1 line
            x[i] = __ldg(emb4 + (size_t)c * 16 + l16);  // 2 rows per LDG.128
            v[i] = __ldg(vals + idx);
        }
        #pragma unroll
        for (int i = 0; i < PAIRS; i++) {
            const int eidx = e + 2 * i + half;
            const float vv = (eidx < end) ? v[i] : 0.0f;  // FSEL, no branch
            acc.x = fmaf(vv, x[i].x, acc.x);
            acc.y = fmaf(vv, x[i].y, acc.y);
            acc.z = fmaf(vv, x[i].z, acc.z);
            acc.w = fmaf(vv, x[i].w, acc.w);
        }
    }

    // Combine the two half-warp partial sums (odd-edge half -> even half).
    acc.x += __shfl_down_sync(0xffffffffu, acc.x, 16);
    acc.y += __shfl_down_sync(0xffffffffu, acc.y, 16);
    acc.z += __shfl_down_sync(0xffffffffu, acc.z, 16);
    acc.w += __shfl_down_sync(0xffffffffu, acc.w, 16);

    // Lanes 0-15 store the full 256B row (coalesced). Empty rows write zeros
    // over the 0xAA poison.
    if (half == 0)
        reinterpret_cast<float4*>(out)[(size_t)row * 16 + l16] = acc;
}

extern "C" void kernel_launch(void* const* d_in, const int* in_sizes, int n_in,
                              void* d_out, int out_size) {
    const int*   row_idx = (const int*)  d_in[0];
    const int*   col_idx = (const int*)  d_in[1];
    const float* vals    = (const float*)d_in[2];
    const float* embeds  = (const float*)d_in[3];
    float*       out     = (float*)d_out;

    build_row_ptr_kernel<<<(N_NODES + 1 + 255) / 256, 256>>>(row_idx);

    const int blocks = N_NODES / ROWS_PER_BLOCK;   // 6250
    gcn_spmm_kernel<<<blocks, ROWS_PER_BLOCK * 32>>>(col_idx, vals, embeds, out);
}